// round 11
// baseline (speedup 1.0000x reference)
#include <cuda_runtime.h>
#include <cuda_bf16.h>
#include <cuda_fp16.h>
#include <cstdint>

// Problem constants
#define N_NODES 100000
#define E_EDGES 1600000
#define F_IN 64
#define H_DIM 128

// ---------------- device scratch (no runtime allocation allowed) ----------------
__device__ int    g_cnt[N_NODES];
__device__ int    g_off[N_NODES];
__device__ int    g_cur[N_NODES];
__device__ int    g_srcs[E_EDGES];
__device__ volatile int g_blk_agg[128];
__device__ volatile int g_blk_pfx[128];
__device__ volatile int g_blk_flag[128];   // 0=none, 1=agg ready, 2=pfx ready
__device__ __half g_x_half[(size_t)N_NODES * F_IN];
__device__ __half g_h_half[(size_t)N_NODES * H_DIM];
__device__ __half g_mean1h[(size_t)N_NODES * F_IN];
__device__ __half g_mean2h[(size_t)N_NODES * H_DIM];

// ---------------- prep: zero counters + scan flags + convert x -> fp16 --------
__global__ void prep_kernel(const float* __restrict__ x) {
    int i = blockIdx.x * blockDim.x + threadIdx.x;
    if (i < N_NODES) g_cnt[i] = 0;
    if (i < 128) { g_blk_flag[i] = 0; g_blk_agg[i] = 0; g_blk_pfx[i] = 0; }
    if (i < N_NODES * (F_IN / 8)) {
        float4 f0 = ((const float4*)x)[i * 2 + 0];
        float4 f1 = ((const float4*)x)[i * 2 + 1];
        __half2 h0 = __floats2half2_rn(f0.x, f0.y);
        __half2 h1 = __floats2half2_rn(f0.z, f0.w);
        __half2 h2 = __floats2half2_rn(f1.x, f1.y);
        __half2 h3 = __floats2half2_rn(f1.z, f1.w);
        uint4 u;
        u.x = *(unsigned*)&h0; u.y = *(unsigned*)&h1;
        u.z = *(unsigned*)&h2; u.w = *(unsigned*)&h3;
        ((uint4*)g_x_half)[i] = u;
    }
}

// ---------------- CSR build ----------------
__global__ void count_kernel(const int* __restrict__ ei) {
    int e4 = blockIdx.x * blockDim.x + threadIdx.x;
    if (e4 < E_EDGES / 4) {
        int4 d = ((const int4*)(ei + E_EDGES))[e4];
        atomicAdd(&g_cnt[d.x], 1);
        atomicAdd(&g_cnt[d.y], 1);
        atomicAdd(&g_cnt[d.z], 1);
        atomicAdd(&g_cnt[d.w], 1);
    }
}

// Single-kernel exclusive scan via decoupled lookback.
// 98 blocks <= 148 SMs -> all resident in wave 1, spin is deadlock-free.
// Flags zeroed by prep_kernel each launch (graph replay safe).
__global__ void scan_kernel() {
    __shared__ int s[1024];
    __shared__ int sprefix;
    int b = blockIdx.x;
    int i = b * 1024 + threadIdx.x;
    int v = (i < N_NODES) ? g_cnt[i] : 0;
    s[threadIdx.x] = v;
    __syncthreads();
    for (int d = 1; d < 1024; d <<= 1) {
        int t = (threadIdx.x >= d) ? s[threadIdx.x - d] : 0;
        __syncthreads();
        s[threadIdx.x] += t;
        __syncthreads();
    }
    int total = s[1023];
    if (threadIdx.x == 0) {
        g_blk_agg[b] = total;
        __threadfence();
        if (b == 0) {
            g_blk_pfx[0] = total;
            __threadfence();
            g_blk_flag[0] = 2;
            sprefix = 0;
        } else {
            g_blk_flag[b] = 1;
            int run = 0;
            int j = b - 1;
            while (j >= 0) {
                int f;
                while ((f = g_blk_flag[j]) == 0) { }
                __threadfence();
                if (f == 2) { run += g_blk_pfx[j]; break; }
                run += g_blk_agg[j];
                j--;
            }
            g_blk_pfx[b] = run + total;
            __threadfence();
            g_blk_flag[b] = 2;
            sprefix = run;
        }
    }
    __syncthreads();
    if (i < N_NODES) {
        int o = sprefix + s[threadIdx.x] - v;   // exclusive
        g_off[i] = o;
        g_cur[i] = o;
    }
}

__global__ void scatter_kernel(const int* __restrict__ ei) {
    int e4 = blockIdx.x * blockDim.x + threadIdx.x;
    if (e4 < E_EDGES / 4) {
        int4 s = ((const int4*)ei)[e4];
        int4 d = ((const int4*)(ei + E_EDGES))[e4];
        int p0 = atomicAdd(&g_cur[d.x], 1); g_srcs[p0] = s.x;
        int p1 = atomicAdd(&g_cur[d.y], 1); g_srcs[p1] = s.y;
        int p2 = atomicAdd(&g_cur[d.z], 1); g_srcs[p2] = s.z;
        int p3 = atomicAdd(&g_cur[d.w], 1); g_srcs[p3] = s.w;
    }
}

// ---------------- aggregation (mean of src fp16 features, fp32 acc, fp16 out)
// Each lane owns TWO uint4 (32B) per row -> 16 outstanding LDG.128 per batch.
// Next batch's indices are prefetched before accumulating (breaks the
// idx->gather serial dependency).
__device__ __forceinline__ void acc_u4(float* a, uint4 u) {
    float2 f0 = __half22float2(*(__half2*)&u.x);
    float2 f1 = __half22float2(*(__half2*)&u.y);
    float2 f2 = __half22float2(*(__half2*)&u.z);
    float2 f3 = __half22float2(*(__half2*)&u.w);
    a[0] += f0.x; a[1] += f0.y; a[2] += f1.x; a[3] += f1.y;
    a[4] += f2.x; a[5] += f2.y; a[6] += f3.x; a[7] += f3.y;
}

template <int LPN_LOG, int ROW_U4>
__device__ __forceinline__ void agg_body(const __half* __restrict__ feat,
                                         __half* __restrict__ mean) {
    constexpr int LPN = 1 << LPN_LOG;         // lanes per node (= ROW_U4/2)
    int t = blockIdx.x * blockDim.x + threadIdx.x;
    int g0 = t >> LPN_LOG;
    int ngroups = (gridDim.x * blockDim.x) >> LPN_LOG;
    int c = t & (LPN - 1);
    const uint4* f4 = (const uint4*)feat;
    for (int n = g0; n < N_NODES; n += ngroups) {
        int start = g_off[n];
        int deg = g_cnt[n];
        float a[16];
#pragma unroll
        for (int j = 0; j < 16; j++) a[j] = 0.f;
        int nb = deg >> 3;
        if (nb > 0) {
            int p0 = g_srcs[start + 0];
            int p1 = g_srcs[start + 1];
            int p2 = g_srcs[start + 2];
            int p3 = g_srcs[start + 3];
            int p4 = g_srcs[start + 4];
            int p5 = g_srcs[start + 5];
            int p6 = g_srcs[start + 6];
            int p7 = g_srcs[start + 7];
            for (int b = 0; b < nb; b++) {
                int q0 = 0, q1 = 0, q2 = 0, q3 = 0, q4 = 0, q5 = 0, q6 = 0, q7 = 0;
                if (b + 1 < nb) {
                    const int* np = g_srcs + start + (b + 1) * 8;
                    q0 = np[0]; q1 = np[1]; q2 = np[2]; q3 = np[3];
                    q4 = np[4]; q5 = np[5]; q6 = np[6]; q7 = np[7];
                }
                // 16 gathers issued together (8 edges x 2 uint4)
                uint4 vA0 = f4[(size_t)p0 * ROW_U4 + c];
                uint4 vB0 = f4[(size_t)p0 * ROW_U4 + c + LPN];
                uint4 vA1 = f4[(size_t)p1 * ROW_U4 + c];
                uint4 vB1 = f4[(size_t)p1 * ROW_U4 + c + LPN];
                uint4 vA2 = f4[(size_t)p2 * ROW_U4 + c];
                uint4 vB2 = f4[(size_t)p2 * ROW_U4 + c + LPN];
                uint4 vA3 = f4[(size_t)p3 * ROW_U4 + c];
                uint4 vB3 = f4[(size_t)p3 * ROW_U4 + c + LPN];
                uint4 vA4 = f4[(size_t)p4 * ROW_U4 + c];
                uint4 vB4 = f4[(size_t)p4 * ROW_U4 + c + LPN];
                uint4 vA5 = f4[(size_t)p5 * ROW_U4 + c];
                uint4 vB5 = f4[(size_t)p5 * ROW_U4 + c + LPN];
                uint4 vA6 = f4[(size_t)p6 * ROW_U4 + c];
                uint4 vB6 = f4[(size_t)p6 * ROW_U4 + c + LPN];
                uint4 vA7 = f4[(size_t)p7 * ROW_U4 + c];
                uint4 vB7 = f4[(size_t)p7 * ROW_U4 + c + LPN];
                acc_u4(a, vA0); acc_u4(a + 8, vB0);
                acc_u4(a, vA1); acc_u4(a + 8, vB1);
                acc_u4(a, vA2); acc_u4(a + 8, vB2);
                acc_u4(a, vA3); acc_u4(a + 8, vB3);
                acc_u4(a, vA4); acc_u4(a + 8, vB4);
                acc_u4(a, vA5); acc_u4(a + 8, vB5);
                acc_u4(a, vA6); acc_u4(a + 8, vB6);
                acc_u4(a, vA7); acc_u4(a + 8, vB7);
                p0 = q0; p1 = q1; p2 = q2; p3 = q3;
                p4 = q4; p5 = q5; p6 = q6; p7 = q7;
            }
        }
        for (int i = nb * 8; i < deg; i++) {
            int s0 = g_srcs[start + i];
            acc_u4(a, f4[(size_t)s0 * ROW_U4 + c]);
            acc_u4(a + 8, f4[(size_t)s0 * ROW_U4 + c + LPN]);
        }
        float inv = 1.0f / (float)(deg > 0 ? deg : 1);
        __half2 h0 = __floats2half2_rn(a[0] * inv, a[1] * inv);
        __half2 h1 = __floats2half2_rn(a[2] * inv, a[3] * inv);
        __half2 h2 = __floats2half2_rn(a[4] * inv, a[5] * inv);
        __half2 h3 = __floats2half2_rn(a[6] * inv, a[7] * inv);
        uint4 u0;
        u0.x = *(unsigned*)&h0; u0.y = *(unsigned*)&h1;
        u0.z = *(unsigned*)&h2; u0.w = *(unsigned*)&h3;
        __half2 h4 = __floats2half2_rn(a[8] * inv, a[9] * inv);
        __half2 h5 = __floats2half2_rn(a[10] * inv, a[11] * inv);
        __half2 h6 = __floats2half2_rn(a[12] * inv, a[13] * inv);
        __half2 h7 = __floats2half2_rn(a[14] * inv, a[15] * inv);
        uint4 u1;
        u1.x = *(unsigned*)&h4; u1.y = *(unsigned*)&h5;
        u1.z = *(unsigned*)&h6; u1.w = *(unsigned*)&h7;
        ((uint4*)mean)[(size_t)n * ROW_U4 + c] = u0;
        ((uint4*)mean)[(size_t)n * ROW_U4 + c + LPN] = u1;
    }
}

__global__ void agg1_kernel() { agg_body<2, 8>(g_x_half, g_mean1h); }   // 4 lanes/node
__global__ void agg2_kernel() { agg_body<3, 16>(g_h_half, g_mean2h); }  // 8 lanes/node

// ---------------- fp16 tensor-core dual GEMM (m16n8k16) ----------------
__device__ __forceinline__ void mma_f16(float* acc, unsigned a0, unsigned a1,
                                        unsigned a2, unsigned a3,
                                        unsigned b0, unsigned b1) {
    asm volatile(
        "mma.sync.aligned.m16n8k16.row.col.f32.f16.f16.f32 "
        "{%0,%1,%2,%3}, {%4,%5,%6,%7}, {%8,%9}, {%0,%1,%2,%3};"
        : "+f"(acc[0]), "+f"(acc[1]), "+f"(acc[2]), "+f"(acc[3])
        : "r"(a0), "r"(a1), "r"(a2), "r"(a3), "r"(b0), "r"(b1));
}

template <int K, int RELU, int OUT_HALF>
__global__ __launch_bounds__(256) void mma_gemm_kernel(
    const __half* __restrict__ Amean, const __half* __restrict__ Aself,
    const float* __restrict__ Wl, const float* __restrict__ bl,
    const float* __restrict__ Wr, void* __restrict__ out_v)
{
    constexpr int KK = 2 * K;
    constexpr int NCHUNK = KK / 64;
    constexpr int NKS = KK / 16;
    constexpr int NFRAG = NKS * 16;
    extern __shared__ unsigned smu[];
    unsigned* Bs = smu;                       // NFRAG * 64 u32 (half2 pairs)
    unsigned* As = smu + NFRAG * 64;          // 128 rows * 36 u32 (fp16)

    const int tid = threadIdx.x;
    const int lane = tid & 31;
    const int warp = tid >> 5;
    const int wr = warp & 1;
    const int wc = warp >> 1;
    const int gid = lane >> 2;
    const int tig = lane & 3;

    for (int idx = tid; idx < NFRAG * 64; idx += 256) {
        int frag = idx >> 6;
        int rem = idx & 63;
        int l = rem >> 1;
        int reg = rem & 1;
        int s = frag >> 4;
        int nt = frag & 15;
        int n = nt * 8 + (l >> 2);
        int k0 = s * 16 + (l & 3) * 2 + reg * 8;
        float v0, v1;
        if (k0 < K) { v0 = Wl[n * K + k0]; v1 = Wl[n * K + k0 + 1]; }
        else        { v0 = Wr[n * K + k0 - K]; v1 = Wr[n * K + k0 - K + 1]; }
        __half2 h = __floats2half2_rn(v0, v1);
        Bs[idx] = *(unsigned*)&h;
    }

    const int numTiles = (N_NODES + 127) / 128;   // 782
    for (int t = blockIdx.x; t < numTiles; t += gridDim.x) {
        int row0 = t * 128;
        float acc[4][4][4];
#pragma unroll
        for (int mt = 0; mt < 4; mt++)
#pragma unroll
            for (int nt = 0; nt < 4; nt++)
#pragma unroll
                for (int r = 0; r < 4; r++) acc[mt][nt][r] = 0.f;

        for (int c = 0; c < NCHUNK; c++) {
            bool isMean = (c * 64 < K);
            const __half* src = isMean ? Amean : Aself;
            int coff = isMean ? c * 64 : c * 64 - K;
            __syncthreads();
#pragma unroll
            for (int i = 0; i < 4; i++) {
                int item = tid + i * 256;
                int r = item >> 3;
                int j = item & 7;
                int grow = row0 + r;
                uint4 u = make_uint4(0, 0, 0, 0);
                if (grow < N_NODES)
                    u = *(const uint4*)(src + (size_t)grow * K + coff + j * 8);
                *(uint4*)(As + r * 36 + j * 4) = u;
            }
            __syncthreads();

#pragma unroll
            for (int s = 0; s < 4; s++) {
                unsigned af[4][4];
#pragma unroll
                for (int mt = 0; mt < 4; mt++) {
                    int r0 = wr * 64 + mt * 16 + gid;
                    af[mt][0] = As[(r0)     * 36 + s * 8 + tig];
                    af[mt][1] = As[(r0 + 8) * 36 + s * 8 + tig];
                    af[mt][2] = As[(r0)     * 36 + s * 8 + tig + 4];
                    af[mt][3] = As[(r0 + 8) * 36 + s * 8 + tig + 4];
                }
                int sg = c * 4 + s;
#pragma unroll
                for (int nt = 0; nt < 4; nt++) {
                    uint2 b = *(const uint2*)(Bs + (sg * 16 + wc * 4 + nt) * 64 + lane * 2);
#pragma unroll
                    for (int mt = 0; mt < 4; mt++)
                        mma_f16(acc[mt][nt], af[mt][0], af[mt][1], af[mt][2], af[mt][3],
                                b.x, b.y);
                }
            }
        }

#pragma unroll
        for (int mt = 0; mt < 4; mt++) {
            int r0 = row0 + wr * 64 + mt * 16 + gid;
            int r1 = r0 + 8;
#pragma unroll
            for (int nt = 0; nt < 4; nt++) {
                int col = wc * 32 + nt * 8 + tig * 2;
                float2 bb = *(const float2*)(bl + col);
                float c0 = acc[mt][nt][0] + bb.x;
                float c1 = acc[mt][nt][1] + bb.y;
                float c2 = acc[mt][nt][2] + bb.x;
                float c3 = acc[mt][nt][3] + bb.y;
                if (RELU) {
                    c0 = fmaxf(c0, 0.f); c1 = fmaxf(c1, 0.f);
                    c2 = fmaxf(c2, 0.f); c3 = fmaxf(c3, 0.f);
                }
                if (OUT_HALF) {
                    __half* o = (__half*)out_v;
                    __half2 p0 = __floats2half2_rn(c0, c1);
                    __half2 p1 = __floats2half2_rn(c2, c3);
                    if (r0 < N_NODES) *(__half2*)(o + (size_t)r0 * 128 + col) = p0;
                    if (r1 < N_NODES) *(__half2*)(o + (size_t)r1 * 128 + col) = p1;
                } else {
                    float* o = (float*)out_v;
                    if (r0 < N_NODES)
                        *(float2*)(o + (size_t)r0 * 128 + col) = make_float2(c0, c1);
                    if (r1 < N_NODES)
                        *(float2*)(o + (size_t)r1 * 128 + col) = make_float2(c2, c3);
                }
            }
        }
    }
}

// ---------------- launch ----------------
extern "C" void kernel_launch(void* const* d_in, const int* in_sizes, int n_in,
                              void* d_out, int out_size)
{
    const float* x   = (const float*)d_in[0];
    const int*   ei  = (const int*)d_in[1];
    const float* Wl1 = (const float*)d_in[2];
    const float* bl1 = (const float*)d_in[3];
    const float* Wr1 = (const float*)d_in[4];
    const float* Wl2 = (const float*)d_in[5];
    const float* bl2 = (const float*)d_in[6];
    const float* Wr2 = (const float*)d_in[7];
    float* out = (float*)d_out;

    const int SMEM1 = (8 * 16 * 64) * 4 + 128 * 36 * 4;    // 51200 B
    const int SMEM2 = (16 * 16 * 64) * 4 + 128 * 36 * 4;   // 83968 B

    static bool attr_done = false;
    if (!attr_done) {
        cudaFuncSetAttribute(mma_gemm_kernel<64, 1, 1>,
                             cudaFuncAttributeMaxDynamicSharedMemorySize, SMEM1);
        cudaFuncSetAttribute(mma_gemm_kernel<128, 0, 0>,
                             cudaFuncAttributeMaxDynamicSharedMemorySize, SMEM2);
        attr_done = true;
    }

    const int NBLK = (N_NODES + 1023) / 1024;   // 98

    prep_kernel<<<(N_NODES * (F_IN / 8) + 255) / 256, 256>>>(x);
    count_kernel<<<(E_EDGES / 4 + 255) / 256, 256>>>(ei);
    scan_kernel<<<NBLK, 1024>>>();
    scatter_kernel<<<(E_EDGES / 4 + 255) / 256, 256>>>(ei);

    static __half *p_m1h = nullptr, *p_m2h = nullptr, *p_xh = nullptr, *p_hh = nullptr;
    if (!p_m1h) {
        cudaGetSymbolAddress((void**)&p_m1h, g_mean1h);
        cudaGetSymbolAddress((void**)&p_m2h, g_mean2h);
        cudaGetSymbolAddress((void**)&p_xh, g_x_half);
        cudaGetSymbolAddress((void**)&p_hh, g_h_half);
    }

    // Layer 1
    agg1_kernel<<<888, 256>>>();
    mma_gemm_kernel<64, 1, 1><<<296, 256, SMEM1>>>(p_m1h, p_xh, Wl1, bl1, Wr1, p_hh);

    // Layer 2
    agg2_kernel<<<888, 256>>>();
    mma_gemm_kernel<128, 0, 0><<<148, 256, SMEM2>>>(p_m2h, p_hh, Wl2, bl2, Wr2, out);
}

// round 12
// speedup vs baseline: 1.0002x; 1.0002x over previous
#include <cuda_runtime.h>
#include <cuda_bf16.h>
#include <cuda_fp16.h>
#include <cstdint>

// Problem constants
#define N_NODES 100000
#define E_EDGES 1600000
#define F_IN 64
#define H_DIM 128

// ---------------- device scratch (no runtime allocation allowed) ----------------
__device__ int    g_cnt[N_NODES];
__device__ int    g_off[N_NODES];    // after scatter: off[n] + cnt[n]
__device__ int    g_srcs[E_EDGES];
__device__ volatile int g_blk_agg[128];
__device__ volatile int g_blk_pfx[128];
__device__ volatile int g_blk_flag[128];   // 0=none, 1=agg ready, 2=pfx ready
__device__ __half g_x_half[(size_t)N_NODES * F_IN];
__device__ __half g_h_half[(size_t)N_NODES * H_DIM];
__device__ __half g_mean1h[(size_t)N_NODES * F_IN];
__device__ __half g_mean2h[(size_t)N_NODES * H_DIM];

// ---------------- prep: zero counters + scan flags + convert x -> fp16 --------
__global__ void prep_kernel(const float* __restrict__ x) {
    int i = blockIdx.x * blockDim.x + threadIdx.x;
    if (i < N_NODES) g_cnt[i] = 0;
    if (i < 128) { g_blk_flag[i] = 0; g_blk_agg[i] = 0; g_blk_pfx[i] = 0; }
    if (i < N_NODES * (F_IN / 8)) {
        float4 f0 = ((const float4*)x)[i * 2 + 0];
        float4 f1 = ((const float4*)x)[i * 2 + 1];
        __half2 h0 = __floats2half2_rn(f0.x, f0.y);
        __half2 h1 = __floats2half2_rn(f0.z, f0.w);
        __half2 h2 = __floats2half2_rn(f1.x, f1.y);
        __half2 h3 = __floats2half2_rn(f1.z, f1.w);
        uint4 u;
        u.x = *(unsigned*)&h0; u.y = *(unsigned*)&h1;
        u.z = *(unsigned*)&h2; u.w = *(unsigned*)&h3;
        ((uint4*)g_x_half)[i] = u;
    }
}

// ---------------- CSR build ----------------
// 8 edges per thread: 8 independent atomic chains to hide ATOMG latency.
__global__ void count_kernel(const int* __restrict__ ei) {
    int e8 = blockIdx.x * blockDim.x + threadIdx.x;
    if (e8 < E_EDGES / 8) {
        int4 d0 = ((const int4*)(ei + E_EDGES))[e8 * 2 + 0];
        int4 d1 = ((const int4*)(ei + E_EDGES))[e8 * 2 + 1];
        atomicAdd(&g_cnt[d0.x], 1);
        atomicAdd(&g_cnt[d0.y], 1);
        atomicAdd(&g_cnt[d0.z], 1);
        atomicAdd(&g_cnt[d0.w], 1);
        atomicAdd(&g_cnt[d1.x], 1);
        atomicAdd(&g_cnt[d1.y], 1);
        atomicAdd(&g_cnt[d1.z], 1);
        atomicAdd(&g_cnt[d1.w], 1);
    }
}

// Single-kernel exclusive scan via decoupled lookback.
// 98 blocks <= 148 SMs -> all wave-1 resident, spin is deadlock-free.
// Flags zeroed by prep_kernel each launch (graph replay safe).
__global__ void scan_kernel() {
    __shared__ int s[1024];
    __shared__ int sprefix;
    int b = blockIdx.x;
    int i = b * 1024 + threadIdx.x;
    int v = (i < N_NODES) ? g_cnt[i] : 0;
    s[threadIdx.x] = v;
    __syncthreads();
    for (int d = 1; d < 1024; d <<= 1) {
        int t = (threadIdx.x >= d) ? s[threadIdx.x - d] : 0;
        __syncthreads();
        s[threadIdx.x] += t;
        __syncthreads();
    }
    int total = s[1023];
    if (threadIdx.x == 0) {
        g_blk_agg[b] = total;
        __threadfence();
        if (b == 0) {
            g_blk_pfx[0] = total;
            __threadfence();
            g_blk_flag[0] = 2;
            sprefix = 0;
        } else {
            g_blk_flag[b] = 1;
            int run = 0;
            int j = b - 1;
            while (j >= 0) {
                int f;
                while ((f = g_blk_flag[j]) == 0) { }
                __threadfence();
                if (f == 2) { run += g_blk_pfx[j]; break; }
                run += g_blk_agg[j];
                j--;
            }
            g_blk_pfx[b] = run + total;
            __threadfence();
            g_blk_flag[b] = 2;
            sprefix = run;
        }
    }
    __syncthreads();
    if (i < N_NODES)
        g_off[i] = sprefix + s[threadIdx.x] - v;   // exclusive
}

// Scatter bumps g_off in place; afterwards g_off[n] = orig_off[n] + cnt[n].
// Aggs recover start = g_off[n] - g_cnt[n]. Deterministic across replays
// because scan rewrites g_off each launch.
__global__ void scatter_kernel(const int* __restrict__ ei) {
    int e8 = blockIdx.x * blockDim.x + threadIdx.x;
    if (e8 < E_EDGES / 8) {
        int4 s0 = ((const int4*)ei)[e8 * 2 + 0];
        int4 s1 = ((const int4*)ei)[e8 * 2 + 1];
        int4 d0 = ((const int4*)(ei + E_EDGES))[e8 * 2 + 0];
        int4 d1 = ((const int4*)(ei + E_EDGES))[e8 * 2 + 1];
        int p0 = atomicAdd(&g_off[d0.x], 1);
        int p1 = atomicAdd(&g_off[d0.y], 1);
        int p2 = atomicAdd(&g_off[d0.z], 1);
        int p3 = atomicAdd(&g_off[d0.w], 1);
        int p4 = atomicAdd(&g_off[d1.x], 1);
        int p5 = atomicAdd(&g_off[d1.y], 1);
        int p6 = atomicAdd(&g_off[d1.z], 1);
        int p7 = atomicAdd(&g_off[d1.w], 1);
        g_srcs[p0] = s0.x; g_srcs[p1] = s0.y;
        g_srcs[p2] = s0.z; g_srcs[p3] = s0.w;
        g_srcs[p4] = s1.x; g_srcs[p5] = s1.y;
        g_srcs[p6] = s1.z; g_srcs[p7] = s1.w;
    }
}

// ---------------- aggregation (mean of src fp16 features, fp32 acc, fp16 out)
// R10-proven structure: 8 edges/batch, 1 uint4 per lane, scalar idx loads.
__device__ __forceinline__ void acc_u4(float* a, uint4 u) {
    float2 f0 = __half22float2(*(__half2*)&u.x);
    float2 f1 = __half22float2(*(__half2*)&u.y);
    float2 f2 = __half22float2(*(__half2*)&u.z);
    float2 f3 = __half22float2(*(__half2*)&u.w);
    a[0] += f0.x; a[1] += f0.y; a[2] += f1.x; a[3] += f1.y;
    a[4] += f2.x; a[5] += f2.y; a[6] += f3.x; a[7] += f3.y;
}

template <int LPN_LOG, int ROW_U4>
__device__ __forceinline__ void agg_body(const __half* __restrict__ feat,
                                         __half* __restrict__ mean) {
    int t = blockIdx.x * blockDim.x + threadIdx.x;
    int g0 = t >> LPN_LOG;
    int ngroups = (gridDim.x * blockDim.x) >> LPN_LOG;
    int c = t & ((1 << LPN_LOG) - 1);
    const uint4* f4 = (const uint4*)feat;
    for (int n = g0; n < N_NODES; n += ngroups) {
        int deg = g_cnt[n];
        int start = g_off[n] - deg;   // g_off was bumped by scatter
        float a[8];
#pragma unroll
        for (int j = 0; j < 8; j++) a[j] = 0.f;
        int i = 0;
        for (; i + 8 <= deg; i += 8) {
            int s0 = g_srcs[start + i + 0];
            int s1 = g_srcs[start + i + 1];
            int s2 = g_srcs[start + i + 2];
            int s3 = g_srcs[start + i + 3];
            int s4 = g_srcs[start + i + 4];
            int s5 = g_srcs[start + i + 5];
            int s6 = g_srcs[start + i + 6];
            int s7 = g_srcs[start + i + 7];
            uint4 v0 = f4[(size_t)s0 * ROW_U4 + c];
            uint4 v1 = f4[(size_t)s1 * ROW_U4 + c];
            uint4 v2 = f4[(size_t)s2 * ROW_U4 + c];
            uint4 v3 = f4[(size_t)s3 * ROW_U4 + c];
            uint4 v4 = f4[(size_t)s4 * ROW_U4 + c];
            uint4 v5 = f4[(size_t)s5 * ROW_U4 + c];
            uint4 v6 = f4[(size_t)s6 * ROW_U4 + c];
            uint4 v7 = f4[(size_t)s7 * ROW_U4 + c];
            acc_u4(a, v0); acc_u4(a, v1); acc_u4(a, v2); acc_u4(a, v3);
            acc_u4(a, v4); acc_u4(a, v5); acc_u4(a, v6); acc_u4(a, v7);
        }
        for (; i < deg; i++) {
            int s0 = g_srcs[start + i];
            acc_u4(a, f4[(size_t)s0 * ROW_U4 + c]);
        }
        float inv = 1.0f / (float)(deg > 0 ? deg : 1);
        __half2 h0 = __floats2half2_rn(a[0] * inv, a[1] * inv);
        __half2 h1 = __floats2half2_rn(a[2] * inv, a[3] * inv);
        __half2 h2 = __floats2half2_rn(a[4] * inv, a[5] * inv);
        __half2 h3 = __floats2half2_rn(a[6] * inv, a[7] * inv);
        uint4 u;
        u.x = *(unsigned*)&h0; u.y = *(unsigned*)&h1;
        u.z = *(unsigned*)&h2; u.w = *(unsigned*)&h3;
        ((uint4*)mean)[(size_t)n * ROW_U4 + c] = u;
    }
}

__global__ void agg1_kernel() { agg_body<3, 8>(g_x_half, g_mean1h); }   // 8 lanes/node
__global__ void agg2_kernel() { agg_body<4, 16>(g_h_half, g_mean2h); }  // 16 lanes/node

// ---------------- fp16 tensor-core dual GEMM (m16n8k16) ----------------
__device__ __forceinline__ void mma_f16(float* acc, unsigned a0, unsigned a1,
                                        unsigned a2, unsigned a3,
                                        unsigned b0, unsigned b1) {
    asm volatile(
        "mma.sync.aligned.m16n8k16.row.col.f32.f16.f16.f32 "
        "{%0,%1,%2,%3}, {%4,%5,%6,%7}, {%8,%9}, {%0,%1,%2,%3};"
        : "+f"(acc[0]), "+f"(acc[1]), "+f"(acc[2]), "+f"(acc[3])
        : "r"(a0), "r"(a1), "r"(a2), "r"(a3), "r"(b0), "r"(b1));
}

template <int K, int RELU, int OUT_HALF>
__global__ __launch_bounds__(256) void mma_gemm_kernel(
    const __half* __restrict__ Amean, const __half* __restrict__ Aself,
    const float* __restrict__ Wl, const float* __restrict__ bl,
    const float* __restrict__ Wr, void* __restrict__ out_v)
{
    constexpr int KK = 2 * K;
    constexpr int NCHUNK = KK / 64;
    constexpr int NKS = KK / 16;
    constexpr int NFRAG = NKS * 16;
    extern __shared__ unsigned smu[];
    unsigned* Bs = smu;                       // NFRAG * 64 u32 (half2 pairs)
    unsigned* As = smu + NFRAG * 64;          // 128 rows * 36 u32 (fp16)

    const int tid = threadIdx.x;
    const int lane = tid & 31;
    const int warp = tid >> 5;
    const int wr = warp & 1;
    const int wc = warp >> 1;
    const int gid = lane >> 2;
    const int tig = lane & 3;

    for (int idx = tid; idx < NFRAG * 64; idx += 256) {
        int frag = idx >> 6;
        int rem = idx & 63;
        int l = rem >> 1;
        int reg = rem & 1;
        int s = frag >> 4;
        int nt = frag & 15;
        int n = nt * 8 + (l >> 2);
        int k0 = s * 16 + (l & 3) * 2 + reg * 8;
        float v0, v1;
        if (k0 < K) { v0 = Wl[n * K + k0]; v1 = Wl[n * K + k0 + 1]; }
        else        { v0 = Wr[n * K + k0 - K]; v1 = Wr[n * K + k0 - K + 1]; }
        __half2 h = __floats2half2_rn(v0, v1);
        Bs[idx] = *(unsigned*)&h;
    }

    const int numTiles = (N_NODES + 127) / 128;   // 782
    for (int t = blockIdx.x; t < numTiles; t += gridDim.x) {
        int row0 = t * 128;
        float acc[4][4][4];
#pragma unroll
        for (int mt = 0; mt < 4; mt++)
#pragma unroll
            for (int nt = 0; nt < 4; nt++)
#pragma unroll
                for (int r = 0; r < 4; r++) acc[mt][nt][r] = 0.f;

        for (int c = 0; c < NCHUNK; c++) {
            bool isMean = (c * 64 < K);
            const __half* src = isMean ? Amean : Aself;
            int coff = isMean ? c * 64 : c * 64 - K;
            __syncthreads();
#pragma unroll
            for (int i = 0; i < 4; i++) {
                int item = tid + i * 256;
                int r = item >> 3;
                int j = item & 7;
                int grow = row0 + r;
                uint4 u = make_uint4(0, 0, 0, 0);
                if (grow < N_NODES)
                    u = *(const uint4*)(src + (size_t)grow * K + coff + j * 8);
                *(uint4*)(As + r * 36 + j * 4) = u;
            }
            __syncthreads();

#pragma unroll
            for (int s = 0; s < 4; s++) {
                unsigned af[4][4];
#pragma unroll
                for (int mt = 0; mt < 4; mt++) {
                    int r0 = wr * 64 + mt * 16 + gid;
                    af[mt][0] = As[(r0)     * 36 + s * 8 + tig];
                    af[mt][1] = As[(r0 + 8) * 36 + s * 8 + tig];
                    af[mt][2] = As[(r0)     * 36 + s * 8 + tig + 4];
                    af[mt][3] = As[(r0 + 8) * 36 + s * 8 + tig + 4];
                }
                int sg = c * 4 + s;
#pragma unroll
                for (int nt = 0; nt < 4; nt++) {
                    uint2 b = *(const uint2*)(Bs + (sg * 16 + wc * 4 + nt) * 64 + lane * 2);
#pragma unroll
                    for (int mt = 0; mt < 4; mt++)
                        mma_f16(acc[mt][nt], af[mt][0], af[mt][1], af[mt][2], af[mt][3],
                                b.x, b.y);
                }
            }
        }

#pragma unroll
        for (int mt = 0; mt < 4; mt++) {
            int r0 = row0 + wr * 64 + mt * 16 + gid;
            int r1 = r0 + 8;
#pragma unroll
            for (int nt = 0; nt < 4; nt++) {
                int col = wc * 32 + nt * 8 + tig * 2;
                float2 bb = *(const float2*)(bl + col);
                float c0 = acc[mt][nt][0] + bb.x;
                float c1 = acc[mt][nt][1] + bb.y;
                float c2 = acc[mt][nt][2] + bb.x;
                float c3 = acc[mt][nt][3] + bb.y;
                if (RELU) {
                    c0 = fmaxf(c0, 0.f); c1 = fmaxf(c1, 0.f);
                    c2 = fmaxf(c2, 0.f); c3 = fmaxf(c3, 0.f);
                }
                if (OUT_HALF) {
                    __half* o = (__half*)out_v;
                    __half2 p0 = __floats2half2_rn(c0, c1);
                    __half2 p1 = __floats2half2_rn(c2, c3);
                    if (r0 < N_NODES) *(__half2*)(o + (size_t)r0 * 128 + col) = p0;
                    if (r1 < N_NODES) *(__half2*)(o + (size_t)r1 * 128 + col) = p1;
                } else {
                    float* o = (float*)out_v;
                    if (r0 < N_NODES)
                        *(float2*)(o + (size_t)r0 * 128 + col) = make_float2(c0, c1);
                    if (r1 < N_NODES)
                        *(float2*)(o + (size_t)r1 * 128 + col) = make_float2(c2, c3);
                }
            }
        }
    }
}

// ---------------- launch ----------------
extern "C" void kernel_launch(void* const* d_in, const int* in_sizes, int n_in,
                              void* d_out, int out_size)
{
    const float* x   = (const float*)d_in[0];
    const int*   ei  = (const int*)d_in[1];
    const float* Wl1 = (const float*)d_in[2];
    const float* bl1 = (const float*)d_in[3];
    const float* Wr1 = (const float*)d_in[4];
    const float* Wl2 = (const float*)d_in[5];
    const float* bl2 = (const float*)d_in[6];
    const float* Wr2 = (const float*)d_in[7];
    float* out = (float*)d_out;

    const int SMEM1 = (8 * 16 * 64) * 4 + 128 * 36 * 4;    // 51200 B
    const int SMEM2 = (16 * 16 * 64) * 4 + 128 * 36 * 4;   // 83968 B

    static bool attr_done = false;
    if (!attr_done) {
        cudaFuncSetAttribute(mma_gemm_kernel<64, 1, 1>,
                             cudaFuncAttributeMaxDynamicSharedMemorySize, SMEM1);
        cudaFuncSetAttribute(mma_gemm_kernel<128, 0, 0>,
                             cudaFuncAttributeMaxDynamicSharedMemorySize, SMEM2);
        attr_done = true;
    }

    const int NBLK = (N_NODES + 1023) / 1024;   // 98

    prep_kernel<<<(N_NODES * (F_IN / 8) + 255) / 256, 256>>>(x);
    count_kernel<<<(E_EDGES / 8 + 255) / 256, 256>>>(ei);
    scan_kernel<<<NBLK, 1024>>>();
    scatter_kernel<<<(E_EDGES / 8 + 255) / 256, 256>>>(ei);

    static __half *p_m1h = nullptr, *p_m2h = nullptr, *p_xh = nullptr, *p_hh = nullptr;
    if (!p_m1h) {
        cudaGetSymbolAddress((void**)&p_m1h, g_mean1h);
        cudaGetSymbolAddress((void**)&p_m2h, g_mean2h);
        cudaGetSymbolAddress((void**)&p_xh, g_x_half);
        cudaGetSymbolAddress((void**)&p_hh, g_h_half);
    }

    // Layer 1
    agg1_kernel<<<888, 256>>>();
    mma_gemm_kernel<64, 1, 1><<<296, 256, SMEM1>>>(p_m1h, p_xh, Wl1, bl1, Wr1, p_hh);

    // Layer 2
    agg2_kernel<<<888, 256>>>();
    mma_gemm_kernel<128, 0, 0><<<148, 256, SMEM2>>>(p_m2h, p_hh, Wl2, bl2, Wr2, out);
}

// round 14
// speedup vs baseline: 1.2115x; 1.2113x over previous
#include <cuda_runtime.h>
#include <cuda_bf16.h>
#include <cuda_fp16.h>
#include <cstdint>

// Problem constants
#define N_NODES 100000
#define E_EDGES 1600000
#define F_IN 64
#define H_DIM 128

// ---------------- device scratch (no runtime allocation allowed) ----------------
__device__ int    g_cnt[N_NODES];
__device__ int    g_off[N_NODES];    // after scatter: off[n] + cnt[n]
__device__ int    g_srcs[E_EDGES];
__device__ int    g_blocksums[128];
__device__ __half g_x_half[(size_t)N_NODES * F_IN];
__device__ __half g_h_half[(size_t)N_NODES * H_DIM];
__device__ __half g_mean1h[(size_t)N_NODES * F_IN];
__device__ __half g_mean2h[(size_t)N_NODES * H_DIM];

// ---------------- prep: zero counters + convert x -> fp16 ----------------
__global__ void prep_kernel(const float* __restrict__ x) {
    int i = blockIdx.x * blockDim.x + threadIdx.x;
    if (i < N_NODES) g_cnt[i] = 0;
    if (i < N_NODES * (F_IN / 8)) {
        float4 f0 = ((const float4*)x)[i * 2 + 0];
        float4 f1 = ((const float4*)x)[i * 2 + 1];
        __half2 h0 = __floats2half2_rn(f0.x, f0.y);
        __half2 h1 = __floats2half2_rn(f0.z, f0.w);
        __half2 h2 = __floats2half2_rn(f1.x, f1.y);
        __half2 h3 = __floats2half2_rn(f1.z, f1.w);
        uint4 u;
        u.x = *(unsigned*)&h0; u.y = *(unsigned*)&h1;
        u.z = *(unsigned*)&h2; u.w = *(unsigned*)&h3;
        ((uint4*)g_x_half)[i] = u;
    }
}

// ---------------- CSR build (4 edges/thread — measured best) ----------------
__global__ void count_kernel(const int* __restrict__ ei) {
    int e4 = blockIdx.x * blockDim.x + threadIdx.x;
    if (e4 < E_EDGES / 4) {
        int4 d = ((const int4*)(ei + E_EDGES))[e4];
        atomicAdd(&g_cnt[d.x], 1);
        atomicAdd(&g_cnt[d.y], 1);
        atomicAdd(&g_cnt[d.z], 1);
        atomicAdd(&g_cnt[d.w], 1);
    }
}

// Two-kernel scan (proven fastest; lookback variant regressed ~16us).
__global__ void scan_local_kernel() {
    __shared__ int s[1024];
    int i = blockIdx.x * 1024 + threadIdx.x;
    int v = (i < N_NODES) ? g_cnt[i] : 0;
    s[threadIdx.x] = v;
    __syncthreads();
    for (int d = 1; d < 1024; d <<= 1) {
        int t = (threadIdx.x >= d) ? s[threadIdx.x - d] : 0;
        __syncthreads();
        s[threadIdx.x] += t;
        __syncthreads();
    }
    if (i < N_NODES) g_off[i] = s[threadIdx.x] - v;
    if (threadIdx.x == 1023) g_blocksums[blockIdx.x] = s[1023];
}

// ALL threads hit EVERY barrier (no divergent barriers).
__global__ void scan_finish_kernel(int nblk) {
    __shared__ int bs[128];
    int tid = threadIdx.x;
    int v = 0;
    if (tid < 128) {
        v = (tid < nblk) ? g_blocksums[tid] : 0;
        bs[tid] = v;
    }
    __syncthreads();
    for (int d = 1; d < 128; d <<= 1) {
        int t = (tid < 128 && tid >= d) ? bs[tid - d] : 0;
        __syncthreads();
        if (tid < 128) bs[tid] += t;
        __syncthreads();
    }
    if (tid < 128) bs[tid] -= v;
    __syncthreads();
    int i = blockIdx.x * 1024 + tid;
    if (i < N_NODES) g_off[i] += bs[blockIdx.x];
}

// Scatter bumps g_off in place; afterwards g_off[n] = orig_off[n] + cnt[n].
// Aggs recover start = g_off[n] - g_cnt[n]. Deterministic across replays
// (scan rewrites g_off from g_cnt each launch).
__global__ void scatter_kernel(const int* __restrict__ ei) {
    int e4 = blockIdx.x * blockDim.x + threadIdx.x;
    if (e4 < E_EDGES / 4) {
        int4 s = ((const int4*)ei)[e4];
        int4 d = ((const int4*)(ei + E_EDGES))[e4];
        int p0 = atomicAdd(&g_off[d.x], 1); g_srcs[p0] = s.x;
        int p1 = atomicAdd(&g_off[d.y], 1); g_srcs[p1] = s.y;
        int p2 = atomicAdd(&g_off[d.z], 1); g_srcs[p2] = s.z;
        int p3 = atomicAdd(&g_off[d.w], 1); g_srcs[p3] = s.w;
    }
}

// ---------------- aggregation (mean of src fp16 features, fp32 acc, fp16 out)
// R10-proven structure: 8 edges/batch, 1 uint4 per lane, scalar idx loads.
__device__ __forceinline__ void acc_u4(float* a, uint4 u) {
    float2 f0 = __half22float2(*(__half2*)&u.x);
    float2 f1 = __half22float2(*(__half2*)&u.y);
    float2 f2 = __half22float2(*(__half2*)&u.z);
    float2 f3 = __half22float2(*(__half2*)&u.w);
    a[0] += f0.x; a[1] += f0.y; a[2] += f1.x; a[3] += f1.y;
    a[4] += f2.x; a[5] += f2.y; a[6] += f3.x; a[7] += f3.y;
}

template <int LPN_LOG, int ROW_U4>
__device__ __forceinline__ void agg_body(const __half* __restrict__ feat,
                                         __half* __restrict__ mean) {
    int t = blockIdx.x * blockDim.x + threadIdx.x;
    int g0 = t >> LPN_LOG;
    int ngroups = (gridDim.x * blockDim.x) >> LPN_LOG;
    int c = t & ((1 << LPN_LOG) - 1);
    const uint4* f4 = (const uint4*)feat;
    for (int n = g0; n < N_NODES; n += ngroups) {
        int deg = g_cnt[n];
        int start = g_off[n] - deg;   // g_off was bumped by scatter
        float a[8];
#pragma unroll
        for (int j = 0; j < 8; j++) a[j] = 0.f;
        int i = 0;
        for (; i + 8 <= deg; i += 8) {
            int s0 = g_srcs[start + i + 0];
            int s1 = g_srcs[start + i + 1];
            int s2 = g_srcs[start + i + 2];
            int s3 = g_srcs[start + i + 3];
            int s4 = g_srcs[start + i + 4];
            int s5 = g_srcs[start + i + 5];
            int s6 = g_srcs[start + i + 6];
            int s7 = g_srcs[start + i + 7];
            uint4 v0 = f4[(size_t)s0 * ROW_U4 + c];
            uint4 v1 = f4[(size_t)s1 * ROW_U4 + c];
            uint4 v2 = f4[(size_t)s2 * ROW_U4 + c];
            uint4 v3 = f4[(size_t)s3 * ROW_U4 + c];
            uint4 v4 = f4[(size_t)s4 * ROW_U4 + c];
            uint4 v5 = f4[(size_t)s5 * ROW_U4 + c];
            uint4 v6 = f4[(size_t)s6 * ROW_U4 + c];
            uint4 v7 = f4[(size_t)s7 * ROW_U4 + c];
            acc_u4(a, v0); acc_u4(a, v1); acc_u4(a, v2); acc_u4(a, v3);
            acc_u4(a, v4); acc_u4(a, v5); acc_u4(a, v6); acc_u4(a, v7);
        }
        for (; i < deg; i++) {
            int s0 = g_srcs[start + i];
            acc_u4(a, f4[(size_t)s0 * ROW_U4 + c]);
        }
        float inv = 1.0f / (float)(deg > 0 ? deg : 1);
        __half2 h0 = __floats2half2_rn(a[0] * inv, a[1] * inv);
        __half2 h1 = __floats2half2_rn(a[2] * inv, a[3] * inv);
        __half2 h2 = __floats2half2_rn(a[4] * inv, a[5] * inv);
        __half2 h3 = __floats2half2_rn(a[6] * inv, a[7] * inv);
        uint4 u;
        u.x = *(unsigned*)&h0; u.y = *(unsigned*)&h1;
        u.z = *(unsigned*)&h2; u.w = *(unsigned*)&h3;
        ((uint4*)mean)[(size_t)n * ROW_U4 + c] = u;
    }
}

__global__ void agg1_kernel() { agg_body<3, 8>(g_x_half, g_mean1h); }   // 8 lanes/node
__global__ void agg2_kernel() { agg_body<4, 16>(g_h_half, g_mean2h); }  // 16 lanes/node

// ---------------- fp16 tensor-core dual GEMM (m16n8k16) ----------------
__device__ __forceinline__ void mma_f16(float* acc, unsigned a0, unsigned a1,
                                        unsigned a2, unsigned a3,
                                        unsigned b0, unsigned b1) {
    asm volatile(
        "mma.sync.aligned.m16n8k16.row.col.f32.f16.f16.f32 "
        "{%0,%1,%2,%3}, {%4,%5,%6,%7}, {%8,%9}, {%0,%1,%2,%3};"
        : "+f"(acc[0]), "+f"(acc[1]), "+f"(acc[2]), "+f"(acc[3])
        : "r"(a0), "r"(a1), "r"(a2), "r"(a3), "r"(b0), "r"(b1));
}

template <int K, int RELU, int OUT_HALF>
__global__ __launch_bounds__(256, 2) void mma_gemm_kernel(
    const __half* __restrict__ Amean, const __half* __restrict__ Aself,
    const float* __restrict__ Wl, const float* __restrict__ bl,
    const float* __restrict__ Wr, void* __restrict__ out_v)
{
    constexpr int KK = 2 * K;
    constexpr int NCHUNK = KK / 64;
    constexpr int NKS = KK / 16;
    constexpr int NFRAG = NKS * 16;
    extern __shared__ unsigned smu[];
    unsigned* Bs = smu;                       // NFRAG * 64 u32 (half2 pairs)
    unsigned* As = smu + NFRAG * 64;          // 128 rows * 36 u32 (fp16)

    const int tid = threadIdx.x;
    const int lane = tid & 31;
    const int warp = tid >> 5;
    const int wr = warp & 1;
    const int wc = warp >> 1;
    const int gid = lane >> 2;
    const int tig = lane & 3;

    for (int idx = tid; idx < NFRAG * 64; idx += 256) {
        int frag = idx >> 6;
        int rem = idx & 63;
        int l = rem >> 1;
        int reg = rem & 1;
        int s = frag >> 4;
        int nt = frag & 15;
        int n = nt * 8 + (l >> 2);
        int k0 = s * 16 + (l & 3) * 2 + reg * 8;
        float v0, v1;
        if (k0 < K) { v0 = Wl[n * K + k0]; v1 = Wl[n * K + k0 + 1]; }
        else        { v0 = Wr[n * K + k0 - K]; v1 = Wr[n * K + k0 - K + 1]; }
        __half2 h = __floats2half2_rn(v0, v1);
        Bs[idx] = *(unsigned*)&h;
    }

    const int numTiles = (N_NODES + 127) / 128;   // 782
    for (int t = blockIdx.x; t < numTiles; t += gridDim.x) {
        int row0 = t * 128;
        float acc[4][4][4];
#pragma unroll
        for (int mt = 0; mt < 4; mt++)
#pragma unroll
            for (int nt = 0; nt < 4; nt++)
#pragma unroll
                for (int r = 0; r < 4; r++) acc[mt][nt][r] = 0.f;

        for (int c = 0; c < NCHUNK; c++) {
            bool isMean = (c * 64 < K);
            const __half* src = isMean ? Amean : Aself;
            int coff = isMean ? c * 64 : c * 64 - K;
            __syncthreads();
#pragma unroll
            for (int i = 0; i < 4; i++) {
                int item = tid + i * 256;
                int r = item >> 3;
                int j = item & 7;
                int grow = row0 + r;
                uint4 u = make_uint4(0, 0, 0, 0);
                if (grow < N_NODES)
                    u = *(const uint4*)(src + (size_t)grow * K + coff + j * 8);
                *(uint4*)(As + r * 36 + j * 4) = u;
            }
            __syncthreads();

#pragma unroll
            for (int s = 0; s < 4; s++) {
                unsigned af[4][4];
#pragma unroll
                for (int mt = 0; mt < 4; mt++) {
                    int r0 = wr * 64 + mt * 16 + gid;
                    af[mt][0] = As[(r0)     * 36 + s * 8 + tig];
                    af[mt][1] = As[(r0 + 8) * 36 + s * 8 + tig];
                    af[mt][2] = As[(r0)     * 36 + s * 8 + tig + 4];
                    af[mt][3] = As[(r0 + 8) * 36 + s * 8 + tig + 4];
                }
                int sg = c * 4 + s;
#pragma unroll
                for (int nt = 0; nt < 4; nt++) {
                    uint2 b = *(const uint2*)(Bs + (sg * 16 + wc * 4 + nt) * 64 + lane * 2);
#pragma unroll
                    for (int mt = 0; mt < 4; mt++)
                        mma_f16(acc[mt][nt], af[mt][0], af[mt][1], af[mt][2], af[mt][3],
                                b.x, b.y);
                }
            }
        }

#pragma unroll
        for (int mt = 0; mt < 4; mt++) {
            int r0 = row0 + wr * 64 + mt * 16 + gid;
            int r1 = r0 + 8;
#pragma unroll
            for (int nt = 0; nt < 4; nt++) {
                int col = wc * 32 + nt * 8 + tig * 2;
                float2 bb = *(const float2*)(bl + col);
                float c0 = acc[mt][nt][0] + bb.x;
                float c1 = acc[mt][nt][1] + bb.y;
                float c2 = acc[mt][nt][2] + bb.x;
                float c3 = acc[mt][nt][3] + bb.y;
                if (RELU) {
                    c0 = fmaxf(c0, 0.f); c1 = fmaxf(c1, 0.f);
                    c2 = fmaxf(c2, 0.f); c3 = fmaxf(c3, 0.f);
                }
                if (OUT_HALF) {
                    __half* o = (__half*)out_v;
                    __half2 p0 = __floats2half2_rn(c0, c1);
                    __half2 p1 = __floats2half2_rn(c2, c3);
                    if (r0 < N_NODES) *(__half2*)(o + (size_t)r0 * 128 + col) = p0;
                    if (r1 < N_NODES) *(__half2*)(o + (size_t)r1 * 128 + col) = p1;
                } else {
                    float* o = (float*)out_v;
                    if (r0 < N_NODES)
                        *(float2*)(o + (size_t)r0 * 128 + col) = make_float2(c0, c1);
                    if (r1 < N_NODES)
                        *(float2*)(o + (size_t)r1 * 128 + col) = make_float2(c2, c3);
                }
            }
        }
    }
}

// ---------------- launch ----------------
extern "C" void kernel_launch(void* const* d_in, const int* in_sizes, int n_in,
                              void* d_out, int out_size)
{
    const float* x   = (const float*)d_in[0];
    const int*   ei  = (const int*)d_in[1];
    const float* Wl1 = (const float*)d_in[2];
    const float* bl1 = (const float*)d_in[3];
    const float* Wr1 = (const float*)d_in[4];
    const float* Wl2 = (const float*)d_in[5];
    const float* bl2 = (const float*)d_in[6];
    const float* Wr2 = (const float*)d_in[7];
    float* out = (float*)d_out;

    const int SMEM1 = (8 * 16 * 64) * 4 + 128 * 36 * 4;    // 51200 B
    const int SMEM2 = (16 * 16 * 64) * 4 + 128 * 36 * 4;   // 83968 B

    static bool attr_done = false;
    if (!attr_done) {
        cudaFuncSetAttribute(mma_gemm_kernel<64, 1, 1>,
                             cudaFuncAttributeMaxDynamicSharedMemorySize, SMEM1);
        cudaFuncSetAttribute(mma_gemm_kernel<128, 0, 0>,
                             cudaFuncAttributeMaxDynamicSharedMemorySize, SMEM2);
        attr_done = true;
    }

    const int NBLK = (N_NODES + 1023) / 1024;   // 98

    prep_kernel<<<(N_NODES * (F_IN / 8) + 255) / 256, 256>>>(x);
    count_kernel<<<(E_EDGES / 4 + 255) / 256, 256>>>(ei);
    scan_local_kernel<<<NBLK, 1024>>>();
    scan_finish_kernel<<<NBLK, 1024>>>(NBLK);
    scatter_kernel<<<(E_EDGES / 4 + 255) / 256, 256>>>(ei);

    static __half *p_m1h = nullptr, *p_m2h = nullptr, *p_xh = nullptr, *p_hh = nullptr;
    if (!p_m1h) {
        cudaGetSymbolAddress((void**)&p_m1h, g_mean1h);
        cudaGetSymbolAddress((void**)&p_m2h, g_mean2h);
        cudaGetSymbolAddress((void**)&p_xh, g_x_half);
        cudaGetSymbolAddress((void**)&p_hh, g_h_half);
    }

    // Layer 1: 2 CTAs/SM
    agg1_kernel<<<888, 256>>>();
    mma_gemm_kernel<64, 1, 1><<<296, 256, SMEM1>>>(p_m1h, p_xh, Wl1, bl1, Wr1, p_hh);

    // Layer 2: 2 CTAs/SM (was 148 — half the SM capacity idled)
    agg2_kernel<<<888, 256>>>();
    mma_gemm_kernel<128, 0, 0><<<296, 256, SMEM2>>>(p_m2h, p_hh, Wl2, bl2, Wr2, out);
}